// round 8
// baseline (speedup 1.0000x reference)
#include <cuda_runtime.h>

// Shapes fixed by the dataset
#define NN   8192
#define D    128
#define PP   256
#define KK   256
#define DEGN 32
#define FFN  16
#define TEMP_INV (1.0f/0.07f)
#define NB_TERM (PP * 2)          // 2 blocks per p, 8 warps, 2 j per warp
#define NB_NEG  (KK / 16)         // 16 negatives per block (2 per warp)
#define GRID    (1 + NB_TERM + NB_NEG)   // block 0 = producer

// Scratch (no allocations allowed)
__device__ __align__(16) float g_zq[D];          // normalized z[query]
__device__ __align__(16) float g_znx[DEGN * D];  // normalized z[N(q)]
__device__ float  g_te[DEGN];         // query-side time encodings
__device__ float  g_core_sum;
__device__ float4 g_part[16 * PP];    // [jg][p]
__device__ float  g_pos[PP];
__device__ float  g_neg[KK];
__device__ unsigned int g_flag;       // producer-done flag (reset by last block)
__device__ unsigned int g_ctr;        // last-block counter (reset by last block)

__device__ __forceinline__ float warpSum(float v) {
#pragma unroll
    for (int o = 16; o; o >>= 1) v += __shfl_xor_sync(0xffffffffu, v, o);
    return v;
}
__device__ __forceinline__ float halfSum(float v) {
#pragma unroll
    for (int o = 8; o; o >>= 1) v += __shfl_xor_sync(0xffffffffu, v, o);
    return v;
}
__device__ __forceinline__ float dot4(float4 a, float4 b) {
    return a.x*b.x + a.y*b.y + a.z*b.z + a.w*b.w;
}
__device__ __forceinline__ unsigned int ctrAddRelease(unsigned int* p) {
    unsigned int old;
    asm volatile("atom.add.release.gpu.global.u32 %0, [%1], 1;"
                 : "=r"(old) : "l"(p) : "memory");
    return old;
}
__device__ __forceinline__ void storeRelease(unsigned int* p, unsigned int v) {
    asm volatile("st.release.gpu.global.u32 [%0], %1;" :: "l"(p), "r"(v) : "memory");
}
__device__ __forceinline__ unsigned int loadAcquire(const unsigned int* p) {
    unsigned int v;
    asm volatile("ld.acquire.gpu.global.u32 %0, [%1];" : "=r"(v) : "l"(p) : "memory");
    return v;
}

// ---------------------------------------------------------------------------
// Single fused kernel with a producer block (b==0) + flag.
// Term blocks (1..NB_TERM): p = (b-1)>>1, warp handles j = ja and ja+8;
// raw gathers are issued BEFORE the flag wait so producer latency overlaps.
// Neg blocks: self-contained, 2 negatives per warp (no wait).
// Last block to arrive folds the final scalar reduction and resets flag+ctr.
// ---------------------------------------------------------------------------
__global__ void __launch_bounds__(256)
k_all(const float* __restrict__ z,
      const float* __restrict__ edge_times,
      const float* __restrict__ cur_t,
      const float* __restrict__ core,
      const float* __restrict__ omega,
      const float* __restrict__ phi,
      const int*   __restrict__ qidx,
      const int*   __restrict__ neg_idxs,
      const int*   __restrict__ nbr_idxs,
      const int*   __restrict__ neighbors,
      float* __restrict__ out)
{
    __shared__ float s_fr[3][8];
    __shared__ unsigned int s_islast;

    const int tid  = threadIdx.x;
    const int lane = tid & 31, warp = tid >> 5;
    const int b    = blockIdx.x;
    const int q    = qidx[0];
    const float ct = cur_t[0];

    if (b == 0) {
        // ---------------- producer block ----------------
        // core proximity sum (independent; do reductions at the end)
        float cd = core[nbr_idxs[tid]] - core[q];

        // warp w owns rows jj = w + 8*i, i = 0..3 (4 independent chains)
        int   jj[4], idx[4];
        float4 r[4];
#pragma unroll
        for (int i = 0; i < 4; i++) {
            jj[i]  = warp + 8 * i;
            idx[i] = neighbors[q * DEGN + jj[i]];
        }
        float et[4];
#pragma unroll
        for (int i = 0; i < 4; i++) {
            et[i] = edge_times[(size_t)q * NN + idx[i]];
            r[i]  = ((const float4*)(z + (size_t)idx[i] * D))[lane];
        }
        // warp 0 also normalizes z_q
        float4 vq = make_float4(0.f, 0.f, 0.f, 0.f);
        if (warp == 0) vq = ((const float4*)(z + (size_t)q * D))[lane];

#pragma unroll
        for (int i = 0; i < 4; i++) {
            float inv = rsqrtf(warpSum(dot4(r[i], r[i])));
            ((float4*)g_znx)[jj[i] * 32 + lane] =
                make_float4(r[i].x*inv, r[i].y*inv, r[i].z*inv, r[i].w*inv);
        }
        if (warp == 0) {
            float inv = rsqrtf(warpSum(dot4(vq, vq)));
            ((float4*)g_zq)[lane] =
                make_float4(vq.x*inv, vq.y*inv, vq.z*inv, vq.w*inv);
        }

        // te's: two halfSum passes, 2 per pass (lanes 0-15 / 16-31)
        const int f = lane & 15;
#pragma unroll
        for (int pass = 0; pass < 2; pass++) {
            const float dt = ct - ((lane < 16) ? et[pass * 2] : et[pass * 2 + 1]);
            float c = (f == 0) ? (omega[0] * dt + phi[0])
                               : __sinf(omega[f] * dt + phi[f]);
            float hc = halfSum(c);
            if (lane == 0)  g_te[jj[pass * 2]]     = hc;
            if (lane == 16) g_te[jj[pass * 2 + 1]] = hc;
        }

        // core sum block-reduce
        {
            __shared__ float red[8];
            float cs = warpSum(cd * cd);
            if (lane == 0) red[warp] = cs;
            __syncthreads();
            if (tid == 0) {
                float t = 0.f;
                for (int i = 0; i < 8; i++) t += red[i];
                g_core_sum = t;
            }
        }
        __syncthreads();
        if (tid == 0) storeRelease(&g_flag, 1u);
    } else if (b <= NB_TERM) {
        // ---------------- term blocks ----------------
        const int bb   = b - 1;
        const int p    = bb >> 1;
        const int half = bb & 1;
        const int ja   = half * 16 + warp;
        const int jb   = ja + 8;
        const int nbp  = nbr_idxs[p];

        // raw gathers FIRST (overlap with producer)
        const int idxa = neighbors[nbp * DEGN + ja];
        const int idxb = neighbors[nbp * DEGN + jb];
        const float eta = edge_times[(size_t)nbp * NN + idxa];
        const float etb = edge_times[(size_t)nbp * NN + idxb];
        const float4 ra = ((const float4*)(z + (size_t)idxa * D))[lane];
        const float4 rb = ((const float4*)(z + (size_t)idxb * D))[lane];
        const float4 vb = ((const float4*)(z + (size_t)nbp  * D))[lane];

        // start the p-invariant butterflies while waiting is unnecessary:
        // these depend only on raw data
        float ssb  = warpSum(dot4(vb, vb));
        float ssra = warpSum(dot4(ra, ra));
        float ssrb = warpSum(dot4(rb, rb));

        // neighbor-side time encodings (raw data only)
        const int   f  = lane & 15;
        const float dt = (lane < 16) ? (ct - eta) : (ct - etb);
        float c = (f == 0) ? (omega[0] * dt + phi[0])
                           : __sinf(omega[f] * dt + phi[f]);
        float hc = halfSum(c);
        const float te2a = __shfl_sync(0xffffffffu, hc, 0);
        const float te2b = __shfl_sync(0xffffffffu, hc, 16);

        // now wait for producer
        while (loadAcquire(&g_flag) == 0) { }

        const float4 zq = ((const float4*)g_zq)[lane];            // unit
        const float4 xa = ((const float4*)g_znx)[ja * 32 + lane]; // unit
        const float4 xb = ((const float4*)g_znx)[jb * 32 + lane]; // unit
        const float te1a = g_te[ja];
        const float te1b = g_te[jb];

        float d1a = warpSum(dot4(xa, vb));
        float d1b = warpSum(dot4(xb, vb));
        float d2a = warpSum(dot4(ra, zq));
        float d2b = warpSum(dot4(rb, zq));

        const float invb = rsqrtf(ssb);
        const float mu1a = 2.f * d1a * invb - 2.f;
        const float mu1b = 2.f * d1b * invb - 2.f;
        const float w1a  = __expf(mu1a * TEMP_INV - te1a);
        const float w1b  = __expf(mu1b * TEMP_INV - te1b);
        const float mu2a = 2.f * d2a * rsqrtf(ssra) - 2.f;
        const float mu2b = 2.f * d2b * rsqrtf(ssrb) - 2.f;
        const float w2a  = __expf(mu2a * TEMP_INV - te2a);
        const float w2b  = __expf(mu2b * TEMP_INV - te2b);

        if (lane == 0)
            g_part[(half * 8 + warp) * PP + p] =
                make_float4(w1a + w1b,
                            w1a * mu1a + w1b * mu1b,
                            w2a + w2b,
                            w2a * mu2a + w2b * mu2b);

        if (half == 0 && warp == 0) {
            float dqb = warpSum(dot4(vb, zq));
            if (lane == 0) {
                float muxy = 2.f * dqb * invb - 2.f;
                float sgm  = 1.f / (1.f + __expf(-muxy));
                g_pos[p] = -__logf(sgm + 1e-8f);
            }
        }
    } else {
        // ---------------- negative blocks (self-contained) ----------------
        const int ka  = (b - 1 - NB_TERM) * 16 + warp * 2;
        const int na  = neg_idxs[ka];
        const int nb2 = neg_idxs[ka + 1];
        const float4 va = ((const float4*)(z + (size_t)na  * D))[lane];
        const float4 vc = ((const float4*)(z + (size_t)nb2 * D))[lane];
        const float4 zr = ((const float4*)(z + (size_t)q   * D))[lane]; // raw
        float ssq = warpSum(dot4(zr, zr));
        float ssa = warpSum(dot4(va, va));
        float ssc = warpSum(dot4(vc, vc));
        float da  = warpSum(dot4(va, zr));
        float dc  = warpSum(dot4(vc, zr));
        if (lane == 0) {
            float invq = rsqrtf(ssq);
            float mua = 2.f * da * invq * rsqrtf(ssa) - 2.f;
            float muc = 2.f * dc * invq * rsqrtf(ssc) - 2.f;
            g_neg[ka]     = -__logf(1.f - 1.f / (1.f + __expf(-mua)) + 1e-8f);
            g_neg[ka + 1] = -__logf(1.f - 1.f / (1.f + __expf(-muc)) + 1e-8f);
        }
    }

    // ---- last-block gate ----
    __syncthreads();
    if (tid == 0) {
        unsigned int t = ctrAddRelease(&g_ctr);
        s_islast = (t == (unsigned int)(GRID - 1));
    }
    __syncthreads();
    if (s_islast) {
        // thread tid owns p = tid (and negative k = tid); coalesced reads
        float W1 = 0.f, WM1 = 0.f, W2 = 0.f, WM2 = 0.f;
#pragma unroll
        for (int jg = 0; jg < 16; jg++) {
            float4 a = __ldcg(&g_part[jg * PP + tid]);
            W1 += a.x; WM1 += a.y; W2 += a.z; WM2 += a.w;
        }
        float term1 = WM1 / (W1 + 1e-8f);
        float term2 = WM2 / (W2 + 1e-8f);
        float d  = term1 + term2;            // lambda_T - lambda_S
        float ad = fabsf(d);
        float al = (ad < 1.f) ? 0.5f * d * d : ad - 0.5f;

        float a  = warpSum(al);
        float sp = warpSum(__ldcg(g_pos + tid));
        float sn = warpSum(__ldcg(g_neg + tid));
        if (lane == 0) {
            s_fr[0][warp] = a; s_fr[1][warp] = sp; s_fr[2][warp] = sn;
        }
        __syncthreads();
        if (tid == 0) {
            float A = 0.f, P = 0.f, Ng = 0.f;
#pragma unroll
            for (int i = 0; i < 8; i++) {
                A += s_fr[0][i]; P += s_fr[1][i]; Ng += s_fr[2][i];
            }
            out[0] = P / PP + Ng / KK
                   + 0.1f * (g_core_sum / PP)
                   + 0.1f * (A / PP);
            g_ctr  = 0;   // reset for next graph replay
            g_flag = 0;   // (safe: every block already passed its wait)
        }
    }
}

// ---------------------------------------------------------------------------
extern "C" void kernel_launch(void* const* d_in, const int* in_sizes, int n_in,
                              void* d_out, int out_size)
{
    const float* z          = (const float*)d_in[0];
    const float* edge_times = (const float*)d_in[1];
    const float* cur_t      = (const float*)d_in[2];
    const float* core       = (const float*)d_in[3];
    const float* omega      = (const float*)d_in[4];
    const float* phi        = (const float*)d_in[5];
    const int*   qidx       = (const int*)d_in[6];
    const int*   neg_idxs   = (const int*)d_in[7];
    const int*   nbr_idxs   = (const int*)d_in[8];
    const int*   neighbors  = (const int*)d_in[9];

    k_all<<<GRID, 256>>>(z, edge_times, cur_t, core, omega, phi,
                         qidx, neg_idxs, nbr_idxs, neighbors, (float*)d_out);
}

// round 9
// speedup vs baseline: 1.1509x; 1.1509x over previous
#include <cuda_runtime.h>

// Shapes fixed by the dataset
#define NN   8192
#define D    128
#define PP   256
#define KK   256
#define DEGN 32
#define FFN  16
#define TEMP_INV (1.0f/0.07f)
#define NB_TERM (PP * 2)          // 2 blocks per p, 8 warps, 2 j per warp
#define NB_NEG  (KK / 16)         // 16 negatives per block (2 per warp)
#define GRID    (1 + NB_TERM + NB_NEG)   // block 0 = producer (not waited on)

// Scratch (no allocations allowed)
__device__ float  g_invsx[DEGN];      // rsqrt(||z[N(q)[j]]||^2)
__device__ float  g_te1[DEGN];        // query-side time encodings
__device__ float  g_invq;             // rsqrt(||z[q]||^2)
__device__ float  g_core_sum;
__device__ float4 g_p3[DEGN * PP];    // [j][p] = {s1, s2, te2, unused}
__device__ float  g_posdot[PP];       // dot(vb,zq_raw)*rsqrt(ssb)
__device__ float  g_neg[KK];
__device__ unsigned int g_ctr;        // reset by last block each launch

__device__ __forceinline__ float warpSum(float v) {
#pragma unroll
    for (int o = 16; o; o >>= 1) v += __shfl_xor_sync(0xffffffffu, v, o);
    return v;
}
__device__ __forceinline__ float halfSum(float v) {      // 16-lane segments
#pragma unroll
    for (int o = 8; o; o >>= 1) v += __shfl_xor_sync(0xffffffffu, v, o);
    return v;
}
__device__ __forceinline__ float octSum(float v) {       // 8-lane segments
#pragma unroll
    for (int o = 4; o; o >>= 1) v += __shfl_xor_sync(0xffffffffu, v, o);
    return v;
}
__device__ __forceinline__ float dot4(float4 a, float4 b) {
    return a.x*b.x + a.y*b.y + a.z*b.z + a.w*b.w;
}
__device__ __forceinline__ unsigned int ctrAddAcqRel(unsigned int* p) {
    unsigned int old;
    asm volatile("atom.add.acq_rel.gpu.global.u32 %0, [%1], 1;"
                 : "=r"(old) : "l"(p) : "memory");
    return old;
}

// ---------------------------------------------------------------------------
// Single fused kernel, NO inter-block waiting.
//  b == 0             : producer — p-invariant scalars (invsx, te1, invq, core)
//  1 .. NB_TERM       : term blocks — raw linear partials only (no producer dep)
//  NB_TERM+1 ..       : negative blocks — self-contained
//  last block to gate : all nonlinear math + final scalar reduction
// ---------------------------------------------------------------------------
__global__ void __launch_bounds__(256)
k_all(const float* __restrict__ z,
      const float* __restrict__ edge_times,
      const float* __restrict__ cur_t,
      const float* __restrict__ core,
      const float* __restrict__ omega,
      const float* __restrict__ phi,
      const int*   __restrict__ qidx,
      const int*   __restrict__ neg_idxs,
      const int*   __restrict__ nbr_idxs,
      const int*   __restrict__ neighbors,
      float* __restrict__ out)
{
    __shared__ float s_fr[3][8];
    __shared__ float s_red[8];
    __shared__ unsigned int s_islast;

    const int tid  = threadIdx.x;
    const int lane = tid & 31, warp = tid >> 5;
    const int b    = blockIdx.x;
    const int q    = qidx[0];
    const float ct = cur_t[0];

    if (b == 0) {
        // ---------------- producer block (nobody waits on it) ----------------
        // warp w owns rows j = w + 8i, i = 0..3
        const int j0 = warp, j1 = warp + 8, j2 = warp + 16, j3 = warp + 24;
        const int i0 = neighbors[q * DEGN + j0];
        const int i1 = neighbors[q * DEGN + j1];
        const int i2 = neighbors[q * DEGN + j2];
        const int i3 = neighbors[q * DEGN + j3];
        const float e0 = edge_times[(size_t)q * NN + i0];
        const float e1 = edge_times[(size_t)q * NN + i1];
        const float e2 = edge_times[(size_t)q * NN + i2];
        const float e3 = edge_times[(size_t)q * NN + i3];
        const float4 r0 = ((const float4*)(z + (size_t)i0 * D))[lane];
        const float4 r1 = ((const float4*)(z + (size_t)i1 * D))[lane];
        const float4 r2 = ((const float4*)(z + (size_t)i2 * D))[lane];
        const float4 r3 = ((const float4*)(z + (size_t)i3 * D))[lane];

        float s0 = warpSum(dot4(r0, r0));
        float s1 = warpSum(dot4(r1, r1));
        float s2 = warpSum(dot4(r2, r2));
        float s3 = warpSum(dot4(r3, r3));
        if (lane == 0) {
            g_invsx[j0] = rsqrtf(s0);
            g_invsx[j1] = rsqrtf(s1);
            g_invsx[j2] = rsqrtf(s2);
            g_invsx[j3] = rsqrtf(s3);
        }

        // te1 for 4 rows in one pass: 8-lane groups, 2 sinusoid terms per lane
        {
            const int g  = lane >> 3;      // 0..3 -> which j
            const int l  = lane & 7;
            const float et = (g == 0) ? e0 : (g == 1) ? e1 : (g == 2) ? e2 : e3;
            const float dt = ct - et;
            const int fA = l;              // 0..7 (0 => linear term)
            const int fB = l + 8;          // 8..15
            float c = ((fA == 0) ? (omega[0] * dt + phi[0])
                                 : __sinf(omega[fA] * dt + phi[fA]))
                    + __sinf(omega[fB] * dt + phi[fB]);
            float te = octSum(c);
            if (l == 0) {
                const int jg = (g == 0) ? j0 : (g == 1) ? j1 : (g == 2) ? j2 : j3;
                g_te1[jg] = te;
            }
        }

        // warp 0: invq
        if (warp == 0) {
            float4 vq = ((const float4*)(z + (size_t)q * D))[lane];
            float ssq = warpSum(dot4(vq, vq));
            if (lane == 0) g_invq = rsqrtf(ssq);
        }

        // core proximity sum (all 256 threads, one p each)
        {
            float cd = core[nbr_idxs[tid]] - core[q];
            float cs = warpSum(cd * cd);
            if (lane == 0) s_red[warp] = cs;
            __syncthreads();
            if (tid == 0) {
                float t = 0.f;
                for (int i = 0; i < 8; i++) t += s_red[i];
                g_core_sum = t;
            }
        }
    } else if (b <= NB_TERM) {
        // ---------------- term blocks (fully independent) ----------------
        const int bb   = b - 1;
        const int p    = bb >> 1;
        const int half = bb & 1;
        const int ja   = half * 16 + warp;
        const int jb   = ja + 8;
        const int nbp  = nbr_idxs[p];

        const int nqa  = neighbors[q   * DEGN + ja];
        const int nqb  = neighbors[q   * DEGN + jb];
        const int idxa = neighbors[nbp * DEGN + ja];
        const int idxb = neighbors[nbp * DEGN + jb];
        const float eta = edge_times[(size_t)nbp * NN + idxa];
        const float etb = edge_times[(size_t)nbp * NN + idxb];

        const float4 xa = ((const float4*)(z + (size_t)nqa  * D))[lane];
        const float4 xb = ((const float4*)(z + (size_t)nqb  * D))[lane];
        const float4 ra = ((const float4*)(z + (size_t)idxa * D))[lane];
        const float4 rb = ((const float4*)(z + (size_t)idxb * D))[lane];
        const float4 vb = ((const float4*)(z + (size_t)nbp  * D))[lane];
        const float4 zq = ((const float4*)(z + (size_t)q    * D))[lane]; // raw

        // neighbor-side time encodings: lanes 0-15 -> ja, 16-31 -> jb
        const int   f  = lane & 15;
        const float dt = (lane < 16) ? (ct - eta) : (ct - etb);
        float c = (f == 0) ? (omega[0] * dt + phi[0])
                           : __sinf(omega[f] * dt + phi[f]);

        // independent butterflies (same count as R7 k1)
        float ssb  = warpSum(dot4(vb, vb));
        float ssra = warpSum(dot4(ra, ra));
        float ssrb = warpSum(dot4(rb, rb));
        float d1a  = warpSum(dot4(xa, vb));
        float d1b  = warpSum(dot4(xb, vb));
        float d2a  = warpSum(dot4(ra, zq));
        float d2b  = warpSum(dot4(rb, zq));
        float hc   = halfSum(c);
        const float te2a = __shfl_sync(0xffffffffu, hc, 0);
        const float te2b = __shfl_sync(0xffffffffu, hc, 16);

        const float invb = rsqrtf(ssb);
        if (lane == 0) {
            g_p3[ja * PP + p] =
                make_float4(d1a * invb, d2a * rsqrtf(ssra), te2a, 0.f);
            g_p3[jb * PP + p] =
                make_float4(d1b * invb, d2b * rsqrtf(ssrb), te2b, 0.f);
        }

        if (half == 0 && warp == 0) {
            float dqb = warpSum(dot4(vb, zq));
            if (lane == 0) g_posdot[p] = dqb * invb;
        }
    } else {
        // ---------------- negative blocks (self-contained) ----------------
        const int ka  = (b - 1 - NB_TERM) * 16 + warp * 2;
        const int na  = neg_idxs[ka];
        const int nb2 = neg_idxs[ka + 1];
        const float4 va = ((const float4*)(z + (size_t)na  * D))[lane];
        const float4 vc = ((const float4*)(z + (size_t)nb2 * D))[lane];
        const float4 zr = ((const float4*)(z + (size_t)q   * D))[lane];
        float ssq = warpSum(dot4(zr, zr));
        float ssa = warpSum(dot4(va, va));
        float ssc = warpSum(dot4(vc, vc));
        float da  = warpSum(dot4(va, zr));
        float dc  = warpSum(dot4(vc, zr));
        if (lane == 0) {
            float invq = rsqrtf(ssq);
            float mua = 2.f * da * invq * rsqrtf(ssa) - 2.f;
            float muc = 2.f * dc * invq * rsqrtf(ssc) - 2.f;
            g_neg[ka]     = -__logf(1.f - 1.f / (1.f + __expf(-mua)) + 1e-8f);
            g_neg[ka + 1] = -__logf(1.f - 1.f / (1.f + __expf(-muc)) + 1e-8f);
        }
    }

    // ---- last-block gate: ALL nonlinear math happens here ----
    __syncthreads();
    if (tid == 0) {
        unsigned int t = ctrAddAcqRel(&g_ctr);
        s_islast = (t == (unsigned int)(GRID - 1));
    }
    __syncthreads();
    if (s_islast) {
        const float invq = __ldcg(&g_invq);
        // thread tid owns p = tid; j-major layout -> coalesced float4 reads
        float W1 = 0.f, WM1 = 0.f, W2 = 0.f, WM2 = 0.f;
#pragma unroll 8
        for (int j = 0; j < DEGN; j++) {
            float4 a = __ldcg(&g_p3[j * PP + tid]);
            float invsx = __ldcg(&g_invsx[j]);     // broadcast
            float te1   = __ldcg(&g_te1[j]);       // broadcast
            float mu1 = 2.f * a.x * invsx - 2.f;
            float w1  = __expf(mu1 * TEMP_INV - te1);
            W1 += w1; WM1 += w1 * mu1;
            float mu2 = 2.f * a.y * invq - 2.f;
            float w2  = __expf(mu2 * TEMP_INV - a.z);
            W2 += w2; WM2 += w2 * mu2;
        }
        float term1 = WM1 / (W1 + 1e-8f);
        float term2 = WM2 / (W2 + 1e-8f);
        float d  = term1 + term2;            // lambda_T - lambda_S
        float ad = fabsf(d);
        float al = (ad < 1.f) ? 0.5f * d * d : ad - 0.5f;

        float muxy = 2.f * __ldcg(&g_posdot[tid]) * invq - 2.f;
        float sgm  = 1.f / (1.f + __expf(-muxy));
        float pl   = -__logf(sgm + 1e-8f);

        float a  = warpSum(al);
        float sp = warpSum(pl);
        float sn = warpSum(__ldcg(&g_neg[tid]));
        if (lane == 0) {
            s_fr[0][warp] = a; s_fr[1][warp] = sp; s_fr[2][warp] = sn;
        }
        __syncthreads();
        if (tid == 0) {
            float A = 0.f, P = 0.f, Ng = 0.f;
#pragma unroll
            for (int i = 0; i < 8; i++) {
                A += s_fr[0][i]; P += s_fr[1][i]; Ng += s_fr[2][i];
            }
            out[0] = P / PP + Ng / KK
                   + 0.1f * (__ldcg(&g_core_sum) / PP)
                   + 0.1f * (A / PP);
            g_ctr = 0;    // reset for next graph replay
        }
    }
}

// ---------------------------------------------------------------------------
extern "C" void kernel_launch(void* const* d_in, const int* in_sizes, int n_in,
                              void* d_out, int out_size)
{
    const float* z          = (const float*)d_in[0];
    const float* edge_times = (const float*)d_in[1];
    const float* cur_t      = (const float*)d_in[2];
    const float* core       = (const float*)d_in[3];
    const float* omega      = (const float*)d_in[4];
    const float* phi        = (const float*)d_in[5];
    const int*   qidx       = (const int*)d_in[6];
    const int*   neg_idxs   = (const int*)d_in[7];
    const int*   nbr_idxs   = (const int*)d_in[8];
    const int*   neighbors  = (const int*)d_in[9];

    k_all<<<GRID, 256>>>(z, edge_times, cur_t, core, omega, phi,
                         qidx, neg_idxs, nbr_idxs, neighbors, (float*)d_out);
}